// round 1
// baseline (speedup 1.0000x reference)
#include <cuda_runtime.h>
#include <cuda_bf16.h>

// Problem constants (shapes fixed by the dataset)
#define B_    256
#define D_    2048
#define N0_   7936
#define NTOT  8192          // N0_ + B_
#define KSEL  128
#define EPS_F 1e-12f

// ---------------- scratch (static device memory; no allocation) --------------
__device__ float g_fsq[B_ * D_];          // f_s^2
__device__ float g_ftq[B_ * D_];          // f_t^2
__device__ float g_qns[B_];               // ||fsq_b||^2
__device__ float g_qnt[B_];               // ||ftq_b||^2
__device__ float g_gn[NTOT];              // gallery(+ftq) row norms^2
__device__ float g_d2t[(size_t)B_ * NTOT];// teacher squared distances
__device__ float g_tval[B_ * KSEL];
__device__ int   g_tidx[B_ * KSEL];
__device__ float g_sval[B_ * KSEL];
__device__ float g_rowmain[B_];
__device__ float g_rowextra[B_];

// ---------------- helpers ----------------------------------------------------
__device__ __forceinline__ float blockReduceSum(float v) {
    int lane = threadIdx.x & 31, wid = threadIdx.x >> 5;
#pragma unroll
    for (int o = 16; o; o >>= 1) v += __shfl_down_sync(0xffffffffu, v, o);
    __shared__ float sh[32];
    if (lane == 0) sh[wid] = v;
    __syncthreads();
    int nw = (blockDim.x + 31) >> 5;
    v = (threadIdx.x < nw) ? sh[threadIdx.x] : 0.f;
    if (wid == 0) {
#pragma unroll
        for (int o = 16; o; o >>= 1) v += __shfl_down_sync(0xffffffffu, v, o);
    }
    return v;  // valid on thread 0
}

// ---------------- kernel 1: square features + query norms --------------------
__global__ void __launch_bounds__(256) sq_kernel(const float* __restrict__ f_s,
                                                 const float* __restrict__ f_t) {
    int r = blockIdx.x;  // 0..511
    const float* src;
    float* dst;
    if (r < B_) { src = f_s + (size_t)r * D_; dst = g_fsq + (size_t)r * D_; }
    else        { src = f_t + (size_t)(r - B_) * D_; dst = g_ftq + (size_t)(r - B_) * D_; }
    float p = 0.f;
    for (int i = threadIdx.x; i < D_; i += 256) {
        float v = src[i];
        float s = v * v;
        dst[i] = s;
        p += s * s;
    }
    float tot = blockReduceSum(p);
    if (threadIdx.x == 0) {
        if (r < B_) g_qns[r] = tot; else g_qnt[r - B_] = tot;
    }
}

// ---------------- kernel 2: gallery (+ appended ftq) row norms ---------------
__global__ void __launch_bounds__(256) galnorm_kernel(const float* __restrict__ gallery,
                                                      const float* __restrict__ f_t) {
    int n = blockIdx.x;  // 0..8191
    float p = 0.f;
    if (n < N0_) {
        const float* g = gallery + (size_t)n * D_;
        for (int i = threadIdx.x; i < D_; i += 256) { float v = g[i]; p += v * v; }
    } else {
        const float* g = f_t + (size_t)(n - N0_) * D_;
        for (int i = threadIdx.x; i < D_; i += 256) { float v = g[i]; float s = v * v; p += s * s; }
    }
    float tot = blockReduceSum(p);
    if (threadIdx.x == 0) g_gn[n] = tot;
}

// ---------------- kernel 3: fp32 SIMT GEMM -> D2t -----------------------------
// Tile 128(M) x 128(N), K-step 8, 256 threads, 8x8 per thread, double-buffered.
#define TM 128
#define TN 128
__global__ void __launch_bounds__(256) gemm_kernel(const float* __restrict__ gallery) {
    const int ntile = blockIdx.x;  // 0..63
    const int mtile = blockIdx.y;  // 0..1
    const float* Bsrc = (ntile * TN < N0_)
                        ? (gallery + (size_t)ntile * TN * D_)
                        : (g_ftq + (size_t)(ntile * TN - N0_) * D_);
    const float* Asrc = g_ftq + (size_t)mtile * TM * D_;

    __shared__ __align__(16) float As[2][8][TM];
    __shared__ __align__(16) float Bs[2][8][TN];

    const int tid  = threadIdx.x;
    const int tx   = tid & 15;
    const int ty   = tid >> 4;
    const int lrow = tid >> 1;          // 0..127
    const int lcol = (tid & 1) << 2;    // 0 or 4

    float acc[8][8];
#pragma unroll
    for (int i = 0; i < 8; i++)
#pragma unroll
        for (int j = 0; j < 8; j++) acc[i][j] = 0.f;

    // prologue: load k-tile 0
    {
        float4 av = *(const float4*)(Asrc + (size_t)lrow * D_ + lcol);
        float4 bv = *(const float4*)(Bsrc + (size_t)lrow * D_ + lcol);
        As[0][lcol + 0][lrow] = av.x; As[0][lcol + 1][lrow] = av.y;
        As[0][lcol + 2][lrow] = av.z; As[0][lcol + 3][lrow] = av.w;
        Bs[0][lcol + 0][lrow] = bv.x; Bs[0][lcol + 1][lrow] = bv.y;
        Bs[0][lcol + 2][lrow] = bv.z; Bs[0][lcol + 3][lrow] = bv.w;
    }
    __syncthreads();

    int buf = 0;
    for (int kb = 8; kb <= D_; kb += 8) {
        float4 an, bn;
        const bool has = (kb < D_);
        if (has) {
            an = *(const float4*)(Asrc + (size_t)lrow * D_ + kb + lcol);
            bn = *(const float4*)(Bsrc + (size_t)lrow * D_ + kb + lcol);
        }
#pragma unroll
        for (int kk = 0; kk < 8; kk++) {
            float4 a0 = *(const float4*)&As[buf][kk][ty * 8];
            float4 a1 = *(const float4*)&As[buf][kk][ty * 8 + 4];
            float4 b0 = *(const float4*)&Bs[buf][kk][tx * 8];
            float4 b1 = *(const float4*)&Bs[buf][kk][tx * 8 + 4];
            float af[8] = {a0.x, a0.y, a0.z, a0.w, a1.x, a1.y, a1.z, a1.w};
            float bf[8] = {b0.x, b0.y, b0.z, b0.w, b1.x, b1.y, b1.z, b1.w};
#pragma unroll
            for (int i = 0; i < 8; i++)
#pragma unroll
                for (int j = 0; j < 8; j++) acc[i][j] += af[i] * bf[j];
        }
        if (has) {
            int nb = buf ^ 1;
            As[nb][lcol + 0][lrow] = an.x; As[nb][lcol + 1][lrow] = an.y;
            As[nb][lcol + 2][lrow] = an.z; As[nb][lcol + 3][lrow] = an.w;
            Bs[nb][lcol + 0][lrow] = bn.x; Bs[nb][lcol + 1][lrow] = bn.y;
            Bs[nb][lcol + 2][lrow] = bn.z; Bs[nb][lcol + 3][lrow] = bn.w;
        }
        __syncthreads();
        buf ^= 1;
    }

    // epilogue: d2 = |q|^2 + |g|^2 - 2*dot
    const int m0 = mtile * TM + ty * 8;
    const int n0 = ntile * TN + tx * 8;
    float gnv[8];
#pragma unroll
    for (int j = 0; j < 8; j++) gnv[j] = g_gn[n0 + j];
#pragma unroll
    for (int i = 0; i < 8; i++) {
        float qn = g_qnt[m0 + i];
        float4 o0, o1;
        o0.x = qn + gnv[0] - 2.f * acc[i][0];
        o0.y = qn + gnv[1] - 2.f * acc[i][1];
        o0.z = qn + gnv[2] - 2.f * acc[i][2];
        o0.w = qn + gnv[3] - 2.f * acc[i][3];
        o1.x = qn + gnv[4] - 2.f * acc[i][4];
        o1.y = qn + gnv[5] - 2.f * acc[i][5];
        o1.z = qn + gnv[6] - 2.f * acc[i][6];
        o1.w = qn + gnv[7] - 2.f * acc[i][7];
        *(float4*)&g_d2t[(size_t)(m0 + i) * NTOT + n0]     = o0;
        *(float4*)&g_d2t[(size_t)(m0 + i) * NTOT + n0 + 4] = o1;
    }
}

// ---------------- kernel 4: exact top-K per row via 2-level radix select -----
template <int NB>
__device__ void find_bin(unsigned* hist, unsigned T, int* s_bin, unsigned* s_pre) {
    constexpr int CH = NB / 256;
    const int tid = threadIdx.x;
    unsigned cnts[CH];
    unsigned local = 0;
#pragma unroll
    for (int c = 0; c < CH; c++) { cnts[c] = hist[tid * CH + c]; local += cnts[c]; }
    unsigned inc = local;
    const int lane = tid & 31, wid = tid >> 5;
#pragma unroll
    for (int off = 1; off < 32; off <<= 1) {
        unsigned n = __shfl_up_sync(0xffffffffu, inc, off);
        if (lane >= off) inc += n;
    }
    __shared__ unsigned wsum[8];
    if (lane == 31) wsum[wid] = inc;
    __syncthreads();
    if (tid == 0) {
        unsigned run = 0;
        for (int w = 0; w < 8; w++) { unsigned t = wsum[w]; wsum[w] = run; run += t; }
    }
    __syncthreads();
    unsigned excl = inc - local + wsum[wid];
    if (excl < T && T <= excl + local) {
        unsigned run = excl;
        for (int c = 0; c < CH; c++) {
            if (run + cnts[c] >= T) { *s_bin = tid * CH + c; *s_pre = run; break; }
            run += cnts[c];
        }
    }
    __syncthreads();
}

__global__ void __launch_bounds__(256) topk_kernel() {
    const int b = blockIdx.x;
    const int tid = threadIdx.x;
    __shared__ unsigned hist[4096];
    __shared__ unsigned long long cand[1024];
    __shared__ int s_bin1, s_bin2;
    __shared__ unsigned s_pre1, s_pre2;
    __shared__ unsigned candCnt;

    const float* row = g_d2t + (size_t)b * NTOT;

    // phase 1: histogram on key bits [31:20]
    for (int i = tid; i < 2048; i += 256) hist[i] = 0;
    if (tid == 0) candCnt = 0;
    __syncthreads();
    for (int i = tid; i < NTOT; i += 256) {
        unsigned key = __float_as_uint(fmaxf(row[i], EPS_F));
        atomicAdd(&hist[key >> 20], 1u);
    }
    __syncthreads();
    find_bin<2048>(hist, KSEL, &s_bin1, &s_pre1);

    // phase 2: refine within bin1 on bits [19:8]
    for (int i = tid; i < 4096; i += 256) hist[i] = 0;
    __syncthreads();
    const unsigned bin1 = (unsigned)s_bin1;
    for (int i = tid; i < NTOT; i += 256) {
        unsigned key = __float_as_uint(fmaxf(row[i], EPS_F));
        if ((key >> 20) == bin1) atomicAdd(&hist[(key >> 8) & 0xFFFu], 1u);
    }
    __syncthreads();
    find_bin<4096>(hist, KSEL - s_pre1, &s_bin2, &s_pre2);

    // phase 3: collect candidates (<= K + small)
    const unsigned bin2 = (unsigned)s_bin2;
    for (int i = tid; i < NTOT; i += 256) {
        unsigned key = __float_as_uint(fmaxf(row[i], EPS_F));
        unsigned hi = key >> 20;
        bool take = (hi < bin1) || (hi == bin1 && ((key >> 8) & 0xFFFu) <= bin2);
        if (take) {
            unsigned pos = atomicAdd(&candCnt, 1u);
            if (pos < 1024) cand[pos] = ((unsigned long long)key << 32) | (unsigned)i;
        }
    }
    __syncthreads();

    // phase 4: pad + bitonic sort (key, idx) ascending
    int M = (int)candCnt;
    if (M > 1024) M = 1024;
    int S = 256;
    while (S < M) S <<= 1;
    for (int i = tid; i < S; i += 256)
        if (i >= M) cand[i] = 0xFFFFFFFFFFFFFFFFULL;
    __syncthreads();
    for (int ksz = 2; ksz <= S; ksz <<= 1) {
        for (int j = ksz >> 1; j > 0; j >>= 1) {
            for (int i = tid; i < S; i += 256) {
                int ixj = i ^ j;
                if (ixj > i) {
                    unsigned long long a = cand[i], c = cand[ixj];
                    bool up = ((i & ksz) == 0);
                    if ((a > c) == up) { cand[i] = c; cand[ixj] = a; }
                }
            }
            __syncthreads();
        }
    }

    // write K smallest: value = sqrt(clipped d2), index
    if (tid < KSEL) {
        unsigned long long e = cand[tid];
        unsigned key = (unsigned)(e >> 32);
        g_tval[b * KSEL + tid] = sqrtf(__uint_as_float(key));
        g_tidx[b * KSEL + tid] = (int)(unsigned)(e & 0xFFFFFFFFu);
    }
}

// ---------------- kernel 5: student distances at teacher's indices -----------
__global__ void __launch_bounds__(256) sdot_kernel(const float* __restrict__ gallery) {
    const int k = blockIdx.x;   // 0..127
    const int b = blockIdx.y;   // 0..255
    const int idx = g_tidx[b * KSEL + k];
    const float* g = (idx < N0_) ? (gallery + (size_t)idx * D_)
                                 : (g_ftq + (size_t)(idx - N0_) * D_);
    const float* q = g_fsq + (size_t)b * D_;
    float p = 0.f;
    for (int i = threadIdx.x; i < D_; i += 256) p += q[i] * g[i];
    float dot = blockReduceSum(p);
    if (threadIdx.x == 0) {
        float d2 = g_qns[b] + g_gn[idx] - 2.f * dot;
        g_sval[b * KSEL + k] = sqrtf(fmaxf(d2, EPS_F));
    }
}

// ---------------- kernel 6: smooth-rank L2 per row ----------------------------
__global__ void __launch_bounds__(128) rank_kernel() {
    const int b = blockIdx.x;
    const int tid = threadIdx.x;  // 128 threads
    __shared__ float tv[KSEL - 1], sv[KSEL - 1];
    if (tid < KSEL - 1) {
        tv[tid] = g_tval[b * KSEL + 1 + tid];
        sv[tid] = g_sval[b * KSEL + 1 + tid];
    }
    __syncthreads();
    float p = 0.f;
    if (tid < KSEL - 1) {
        float ti = tv[tid], si = sv[tid];
        float tr = 0.f, sr = 0.f;
#pragma unroll 4
        for (int j = 0; j < KSEL - 1; j++) {
            tr += fmaxf(ti - tv[j], 0.f);
            sr += fmaxf(si - sv[j], 0.f);
        }
        float d = tr - sr;
        p = d * d;
    }
    float s = blockReduceSum(p);
    if (tid == 0) {
        g_rowextra[b] = sqrtf(s);
        g_rowmain[b]  = fabsf(g_sval[b * KSEL] - g_tval[b * KSEL]);
    }
}

// ---------------- kernel 7: deterministic final reduction ---------------------
__global__ void __launch_bounds__(256) final_kernel(float* __restrict__ out) {
    __shared__ float sm[256], se[256];
    const int t = threadIdx.x;
    sm[t] = g_rowmain[t];
    se[t] = g_rowextra[t];
    __syncthreads();
    for (int s = 128; s > 0; s >>= 1) {
        if (t < s) { sm[t] += sm[t + s]; se[t] += se[t + s]; }
        __syncthreads();
    }
    if (t == 0) {
        float main_loss  = sm[0] / (float)B_;                       // ALPHA = 1
        float extra_loss = (se[0] / (float)B_) / (float)(KSEL - 1); // BETA = 1
        out[0] = main_loss + extra_loss;
    }
}

// ---------------- launch ------------------------------------------------------
extern "C" void kernel_launch(void* const* d_in, const int* in_sizes, int n_in,
                              void* d_out, int out_size) {
    const float* f_s     = (const float*)d_in[0];
    const float* f_t     = (const float*)d_in[1];
    const float* gallery = (const float*)d_in[2];
    float* out = (float*)d_out;

    sq_kernel<<<512, 256>>>(f_s, f_t);
    galnorm_kernel<<<NTOT, 256>>>(gallery, f_t);
    gemm_kernel<<<dim3(NTOT / TN, B_ / TM), 256>>>(gallery);
    topk_kernel<<<B_, 256>>>();
    sdot_kernel<<<dim3(KSEL, B_), 256>>>(gallery);
    rank_kernel<<<B_, 128>>>();
    final_kernel<<<1, 256>>>(out);
}

// round 3
// speedup vs baseline: 1.7527x; 1.7527x over previous
#include <cuda_runtime.h>
#include <cuda_bf16.h>
#include <cstdint>

// Problem constants
#define B_    256
#define D_    2048
#define N0_   7936
#define NTOT  8192
#define KSEL  128
#define EPS_F 1e-12f

// ---------------- scratch ----------------------------------------------------
__device__ float g_fsq[B_ * D_];
__device__ float g_ftq[B_ * D_];
__device__ float g_qns[B_];
__device__ float g_qnt[B_];
__device__ float g_gn[NTOT];
__device__ float g_d2t[(size_t)B_ * NTOT];
__device__ float g_tval[B_ * KSEL];
__device__ int   g_tidx[B_ * KSEL];
__device__ float g_sval[B_ * KSEL];
__device__ float g_rowmain[B_];
__device__ float g_rowextra[B_];

// ---------------- helpers ----------------------------------------------------
__device__ __forceinline__ uint32_t smem_to_u32(const void* p) {
    uint32_t a;
    asm("{ .reg .u64 t; cvta.to.shared.u64 t, %1; cvt.u32.u64 %0, t; }" : "=r"(a) : "l"(p));
    return a;
}

__device__ __forceinline__ float tf32r(float x) {
    uint32_t o;
    asm("cvt.rna.tf32.f32 %0, %1;" : "=r"(o) : "f"(x));
    return __uint_as_float(o);
}

#define LDSM_X4(R, ADDR) \
    asm volatile("ldmatrix.sync.aligned.m8n8.x4.shared.b16 {%0,%1,%2,%3}, [%4];" \
        : "=r"((R)[0]), "=r"((R)[1]), "=r"((R)[2]), "=r"((R)[3]) : "r"(ADDR))

#define MMA_TF32(D, A, B0, B1) \
    asm volatile("mma.sync.aligned.m16n8k8.row.col.f32.tf32.tf32.f32 " \
        "{%0,%1,%2,%3}, {%4,%5,%6,%7}, {%8,%9}, {%0,%1,%2,%3};" \
        : "+f"((D)[0]), "+f"((D)[1]), "+f"((D)[2]), "+f"((D)[3]) \
        : "r"((A)[0]), "r"((A)[1]), "r"((A)[2]), "r"((A)[3]), "r"(B0), "r"(B1))

__device__ __forceinline__ float blockReduceSum(float v) {
    int lane = threadIdx.x & 31, wid = threadIdx.x >> 5;
#pragma unroll
    for (int o = 16; o; o >>= 1) v += __shfl_down_sync(0xffffffffu, v, o);
    __shared__ float sh[32];
    if (lane == 0) sh[wid] = v;
    __syncthreads();
    int nw = (blockDim.x + 31) >> 5;
    v = (threadIdx.x < nw) ? sh[threadIdx.x] : 0.f;
    if (wid == 0) {
#pragma unroll
        for (int o = 16; o; o >>= 1) v += __shfl_down_sync(0xffffffffu, v, o);
    }
    return v;
}

// ---------------- kernel 1: square features + query norms --------------------
__global__ void __launch_bounds__(256) sq_kernel(const float* __restrict__ f_s,
                                                 const float* __restrict__ f_t) {
    int r = blockIdx.x;
    const float* src;
    float* dst;
    if (r < B_) { src = f_s + (size_t)r * D_; dst = g_fsq + (size_t)r * D_; }
    else        { src = f_t + (size_t)(r - B_) * D_; dst = g_ftq + (size_t)(r - B_) * D_; }
    float p = 0.f;
    for (int i = threadIdx.x; i < D_; i += 256) {
        float v = src[i];
        float s = v * v;
        dst[i] = s;
        p += s * s;
    }
    float tot = blockReduceSum(p);
    if (threadIdx.x == 0) {
        if (r < B_) g_qns[r] = tot; else g_qnt[r - B_] = tot;
    }
}

// ---------------- kernel 2: gallery (+ appended ftq) row norms ---------------
__global__ void __launch_bounds__(256) galnorm_kernel(const float* __restrict__ gallery,
                                                      const float* __restrict__ f_t) {
    int n = blockIdx.x;
    float p = 0.f;
    if (n < N0_) {
        const float* g = gallery + (size_t)n * D_;
        for (int i = threadIdx.x; i < D_; i += 256) { float v = g[i]; p += v * v; }
    } else {
        const float* g = f_t + (size_t)(n - N0_) * D_;
        for (int i = threadIdx.x; i < D_; i += 256) { float v = g[i]; float s = v * v; p += s * s; }
    }
    float tot = blockReduceSum(p);
    if (threadIdx.x == 0) g_gn[n] = tot;
}

// ---------------- kernel 3: TF32 mma.sync GEMM -> D2t -------------------------
// CTA 128(M) x 128(N), 8 warps in 2x4, warp tile 64x32, K-chunk 32, double buffer.
// smem per stage: A[128][32] + B[128][32] tf32 with XOR-group swizzle (no pad).
// word(r, k) = r*32 + (((k>>2) ^ (r&7))<<2) + (k&3)
#define KC 32
#define GEMM_SMEM (2 * 8192 * 4)   // bytes

__global__ void __launch_bounds__(256) tf32_gemm_kernel(const float* __restrict__ gallery) {
    extern __shared__ float smem[];  // stage s: A at s*8192, B at s*8192 + 4096 (floats)
    const int tid = threadIdx.x;
    const int ntile = blockIdx.x;    // 0..63
    const int mtile = blockIdx.y;    // 0..1

    // ---- staging mapping: thread -> (row, 16-col half) ----
    const int r  = tid >> 1;
    const int h  = tid & 1;
    const int rx = r & 7;
    const float* aptr = g_ftq + (size_t)(mtile * 128 + r) * D_ + h * 16;
    const int grow = ntile * 128 + r;
    const float* bptr = ((grow < N0_) ? (gallery + (size_t)grow * D_)
                                      : (g_ftq + (size_t)(grow - N0_) * D_)) + h * 16;

    // ---- fragment mapping ----
    const int lane = tid & 31, wid = tid >> 5;
    const int wm = wid >> 2, wn = wid & 3;        // warp grid 2(M) x 4(N)
    const int r_in   = lane & 7;
    const int a_moff = ((lane >> 3) & 1) << 3;
    const int a_koff = (lane >> 4) & 1;
    const int b_noff = ((lane >> 4) & 1) << 3;
    const int b_koff = (lane >> 3) & 1;
    const uint32_t smem_u32 = smem_to_u32(smem);
    const uint32_t arow = (uint32_t)(wm * 64 + r_in + a_moff) * 128u;
    const uint32_t brow = (uint32_t)(wn * 32 + r_in + b_noff) * 128u + 16384u;

    float d[4][4][4];
#pragma unroll
    for (int i = 0; i < 4; i++)
#pragma unroll
        for (int j = 0; j < 4; j++)
#pragma unroll
            for (int q = 0; q < 4; q++) d[i][j][q] = 0.f;

    float4 av[4], bv[4];

    // ---- prologue: load + stage chunk 0 ----
#pragma unroll
    for (int u = 0; u < 4; u++) {
        av[u] = *(const float4*)(aptr + u * 4);
        bv[u] = *(const float4*)(bptr + u * 4);
    }
#pragma unroll
    for (int u = 0; u < 4; u++) {
        const int kg = (((h << 2) + u) ^ rx) << 2;
        float* As = smem + r * 32 + kg;
        float* Bs = As + 4096;
        *(float4*)As = make_float4(tf32r(av[u].x), tf32r(av[u].y), tf32r(av[u].z), tf32r(av[u].w));
        *(float4*)Bs = make_float4(tf32r(bv[u].x), tf32r(bv[u].y), tf32r(bv[u].z), tf32r(bv[u].w));
    }
    __syncthreads();

    const int NCH = D_ / KC;  // 64
    for (int c = 0; c < NCH; ++c) {
        // prefetch next chunk to registers
        if (c + 1 < NCH) {
            const float* ap = aptr + (c + 1) * KC;
            const float* bp = bptr + (c + 1) * KC;
#pragma unroll
            for (int u = 0; u < 4; u++) {
                av[u] = *(const float4*)(ap + u * 4);
                bv[u] = *(const float4*)(bp + u * 4);
            }
        }

        // compute 4 K8 steps from stage (c&1)
        const uint32_t st = (uint32_t)(c & 1) * 32768u;
        const uint32_t abase = smem_u32 + st + arow;
        const uint32_t bbase = smem_u32 + st + brow;
#pragma unroll
        for (int s = 0; s < 4; ++s) {
            const uint32_t ka = (uint32_t)(((2 * s + a_koff) ^ r_in) << 4);
            const uint32_t kb = (uint32_t)(((2 * s + b_koff) ^ r_in) << 4);
            uint32_t a[4][4], bb[2][4];
#pragma unroll
            for (int mi = 0; mi < 4; mi++) LDSM_X4(a[mi], abase + mi * 2048 + ka);
#pragma unroll
            for (int np = 0; np < 2; np++) LDSM_X4(bb[np], bbase + np * 2048 + kb);
#pragma unroll
            for (int mi = 0; mi < 4; mi++) {
                MMA_TF32(d[mi][0], a[mi], bb[0][0], bb[0][1]);
                MMA_TF32(d[mi][1], a[mi], bb[0][2], bb[0][3]);
                MMA_TF32(d[mi][2], a[mi], bb[1][0], bb[1][1]);
                MMA_TF32(d[mi][3], a[mi], bb[1][2], bb[1][3]);
            }
        }

        // stage next chunk
        if (c + 1 < NCH) {
            float* base = smem + ((c + 1) & 1) * 8192 + r * 32;
#pragma unroll
            for (int u = 0; u < 4; u++) {
                const int kg = (((h << 2) + u) ^ rx) << 2;
                float* As = base + kg;
                float* Bs = As + 4096;
                *(float4*)As = make_float4(tf32r(av[u].x), tf32r(av[u].y), tf32r(av[u].z), tf32r(av[u].w));
                *(float4*)Bs = make_float4(tf32r(bv[u].x), tf32r(bv[u].y), tf32r(bv[u].z), tf32r(bv[u].w));
            }
        }
        __syncthreads();
    }

    // ---- epilogue: d2 = |q|^2 + |g|^2 - 2*dot ----
    const int g = lane >> 2, t = lane & 3;
#pragma unroll
    for (int mi = 0; mi < 4; mi++) {
        const int r0 = mtile * 128 + wm * 64 + mi * 16 + g;
        const int r1 = r0 + 8;
        const float qn0 = g_qnt[r0], qn1 = g_qnt[r1];
        float* o0 = g_d2t + (size_t)r0 * NTOT;
        float* o1 = g_d2t + (size_t)r1 * NTOT;
#pragma unroll
        for (int ni = 0; ni < 4; ni++) {
            const int c0 = ntile * 128 + wn * 32 + ni * 8 + 2 * t;
            const float gn0 = g_gn[c0], gn1 = g_gn[c0 + 1];
            float2 v0, v1;
            v0.x = qn0 + gn0 - 2.f * d[mi][ni][0];
            v0.y = qn0 + gn1 - 2.f * d[mi][ni][1];
            v1.x = qn1 + gn0 - 2.f * d[mi][ni][2];
            v1.y = qn1 + gn1 - 2.f * d[mi][ni][3];
            *(float2*)(o0 + c0) = v0;
            *(float2*)(o1 + c0) = v1;
        }
    }
}

// ---------------- kernel 3b: fp32 override of self-match entries -------------
// d2[b][N0+b] is exactly 0 in real arithmetic; compute it in fp32 with a
// GEMM-like accumulation order so the noise distribution matches the reference.
__global__ void __launch_bounds__(256) selffix_kernel() {
    const int b = blockIdx.x;
    const float* q = g_ftq + (size_t)b * D_;
    const int i0 = threadIdx.x * 8;
    float local = 0.f;
#pragma unroll
    for (int j = 0; j < 8; j++) { float v = q[i0 + j]; local += v * v; }
    float dot = blockReduceSum(local);
    if (threadIdx.x == 0) {
        g_d2t[(size_t)b * NTOT + N0_ + b] = g_qnt[b] + g_gn[N0_ + b] - 2.f * dot;
    }
}

// ---------------- kernel 4: exact top-K per row via 2-level radix select -----
template <int NB>
__device__ void find_bin(unsigned* hist, unsigned T, int* s_bin, unsigned* s_pre) {
    constexpr int CH = NB / 256;
    const int tid = threadIdx.x;
    unsigned cnts[CH];
    unsigned local = 0;
#pragma unroll
    for (int c = 0; c < CH; c++) { cnts[c] = hist[tid * CH + c]; local += cnts[c]; }
    unsigned inc = local;
    const int lane = tid & 31, wid = tid >> 5;
#pragma unroll
    for (int off = 1; off < 32; off <<= 1) {
        unsigned n = __shfl_up_sync(0xffffffffu, inc, off);
        if (lane >= off) inc += n;
    }
    __shared__ unsigned wsum[8];
    if (lane == 31) wsum[wid] = inc;
    __syncthreads();
    if (tid == 0) {
        unsigned run = 0;
        for (int w = 0; w < 8; w++) { unsigned t = wsum[w]; wsum[w] = run; run += t; }
    }
    __syncthreads();
    unsigned excl = inc - local + wsum[wid];
    if (excl < T && T <= excl + local) {
        unsigned run = excl;
        for (int c = 0; c < CH; c++) {
            if (run + cnts[c] >= T) { *s_bin = tid * CH + c; *s_pre = run; break; }
            run += cnts[c];
        }
    }
    __syncthreads();
}

__global__ void __launch_bounds__(256) topk_kernel() {
    const int b = blockIdx.x;
    const int tid = threadIdx.x;
    __shared__ unsigned hist[4096];
    __shared__ unsigned long long cand[1024];
    __shared__ int s_bin1, s_bin2;
    __shared__ unsigned s_pre1, s_pre2;
    __shared__ unsigned candCnt;

    const float* row = g_d2t + (size_t)b * NTOT;

    for (int i = tid; i < 2048; i += 256) hist[i] = 0;
    if (tid == 0) candCnt = 0;
    __syncthreads();
    for (int i = tid; i < NTOT; i += 256) {
        unsigned key = __float_as_uint(fmaxf(row[i], EPS_F));
        atomicAdd(&hist[key >> 20], 1u);
    }
    __syncthreads();
    find_bin<2048>(hist, KSEL, &s_bin1, &s_pre1);

    for (int i = tid; i < 4096; i += 256) hist[i] = 0;
    __syncthreads();
    const unsigned bin1 = (unsigned)s_bin1;
    for (int i = tid; i < NTOT; i += 256) {
        unsigned key = __float_as_uint(fmaxf(row[i], EPS_F));
        if ((key >> 20) == bin1) atomicAdd(&hist[(key >> 8) & 0xFFFu], 1u);
    }
    __syncthreads();
    find_bin<4096>(hist, KSEL - s_pre1, &s_bin2, &s_pre2);

    const unsigned bin2 = (unsigned)s_bin2;
    for (int i = tid; i < NTOT; i += 256) {
        unsigned key = __float_as_uint(fmaxf(row[i], EPS_F));
        unsigned hi = key >> 20;
        bool take = (hi < bin1) || (hi == bin1 && ((key >> 8) & 0xFFFu) <= bin2);
        if (take) {
            unsigned pos = atomicAdd(&candCnt, 1u);
            if (pos < 1024) cand[pos] = ((unsigned long long)key << 32) | (unsigned)i;
        }
    }
    __syncthreads();

    int M = (int)candCnt;
    if (M > 1024) M = 1024;
    int S = 256;
    while (S < M) S <<= 1;
    for (int i = tid; i < S; i += 256)
        if (i >= M) cand[i] = 0xFFFFFFFFFFFFFFFFULL;
    __syncthreads();
    for (int ksz = 2; ksz <= S; ksz <<= 1) {
        for (int j = ksz >> 1; j > 0; j >>= 1) {
            for (int i = tid; i < S; i += 256) {
                int ixj = i ^ j;
                if (ixj > i) {
                    unsigned long long a = cand[i], cc = cand[ixj];
                    bool up = ((i & ksz) == 0);
                    if ((a > cc) == up) { cand[i] = cc; cand[ixj] = a; }
                }
            }
            __syncthreads();
        }
    }

    if (tid < KSEL) {
        unsigned long long e = cand[tid];
        unsigned key = (unsigned)(e >> 32);
        g_tval[b * KSEL + tid] = sqrtf(__uint_as_float(key));
        g_tidx[b * KSEL + tid] = (int)(unsigned)(e & 0xFFFFFFFFu);
    }
}

// ---------------- kernel 5: student distances at teacher's indices -----------
__global__ void __launch_bounds__(256) sdot_kernel(const float* __restrict__ gallery) {
    const int k = blockIdx.x;
    const int b = blockIdx.y;
    const int idx = g_tidx[b * KSEL + k];
    const float* g = (idx < N0_) ? (gallery + (size_t)idx * D_)
                                 : (g_ftq + (size_t)(idx - N0_) * D_);
    const float* q = g_fsq + (size_t)b * D_;
    float p = 0.f;
    for (int i = threadIdx.x; i < D_; i += 256) p += q[i] * g[i];
    float dot = blockReduceSum(p);
    if (threadIdx.x == 0) {
        float d2 = g_qns[b] + g_gn[idx] - 2.f * dot;
        g_sval[b * KSEL + k] = sqrtf(fmaxf(d2, EPS_F));
    }
}

// ---------------- kernel 6: smooth-rank L2 per row ----------------------------
__global__ void __launch_bounds__(128) rank_kernel() {
    const int b = blockIdx.x;
    const int tid = threadIdx.x;
    __shared__ float tv[KSEL - 1], sv[KSEL - 1];
    if (tid < KSEL - 1) {
        tv[tid] = g_tval[b * KSEL + 1 + tid];
        sv[tid] = g_sval[b * KSEL + 1 + tid];
    }
    __syncthreads();
    float p = 0.f;
    if (tid < KSEL - 1) {
        float ti = tv[tid], si = sv[tid];
        float tr = 0.f, sr = 0.f;
#pragma unroll 4
        for (int j = 0; j < KSEL - 1; j++) {
            tr += fmaxf(ti - tv[j], 0.f);
            sr += fmaxf(si - sv[j], 0.f);
        }
        float dd = tr - sr;
        p = dd * dd;
    }
    float s = blockReduceSum(p);
    if (tid == 0) {
        g_rowextra[b] = sqrtf(s);
        g_rowmain[b]  = fabsf(g_sval[b * KSEL] - g_tval[b * KSEL]);
    }
}

// ---------------- kernel 7: deterministic final reduction ---------------------
__global__ void __launch_bounds__(256) final_kernel(float* __restrict__ out) {
    __shared__ float sm[256], se[256];
    const int t = threadIdx.x;
    sm[t] = g_rowmain[t];
    se[t] = g_rowextra[t];
    __syncthreads();
    for (int s = 128; s > 0; s >>= 1) {
        if (t < s) { sm[t] += sm[t + s]; se[t] += se[t + s]; }
        __syncthreads();
    }
    if (t == 0) {
        float main_loss  = sm[0] / (float)B_;
        float extra_loss = (se[0] / (float)B_) / (float)(KSEL - 1);
        out[0] = main_loss + extra_loss;
    }
}

// ---------------- launch ------------------------------------------------------
extern "C" void kernel_launch(void* const* d_in, const int* in_sizes, int n_in,
                              void* d_out, int out_size) {
    const float* f_s     = (const float*)d_in[0];
    const float* f_t     = (const float*)d_in[1];
    const float* gallery = (const float*)d_in[2];
    float* out = (float*)d_out;

    cudaFuncSetAttribute(tf32_gemm_kernel, cudaFuncAttributeMaxDynamicSharedMemorySize, GEMM_SMEM);

    sq_kernel<<<512, 256>>>(f_s, f_t);
    galnorm_kernel<<<NTOT, 256>>>(gallery, f_t);
    tf32_gemm_kernel<<<dim3(NTOT / 128, B_ / 128), 256, GEMM_SMEM>>>(gallery);
    selffix_kernel<<<B_, 256>>>();
    topk_kernel<<<B_, 256>>>();
    sdot_kernel<<<dim3(KSEL, B_), 256>>>(gallery);
    rank_kernel<<<B_, 128>>>();
    final_kernel<<<1, 256>>>(out);
}

// round 4
// speedup vs baseline: 2.5607x; 1.4611x over previous
#include <cuda_runtime.h>
#include <cuda_bf16.h>
#include <cstdint>

// Problem constants
#define B_    256
#define D_    2048
#define N0_   7936
#define NTOT  8192
#define KSEL  128
#define EPS_F 1e-12f

// ---------------- scratch ----------------------------------------------------
__device__ float g_fsq[B_ * D_];
__device__ float g_ftq[B_ * D_];
__device__ float g_qns[B_];
__device__ float g_qnt[B_];
__device__ float g_gn[NTOT];
__device__ float g_d2t[(size_t)B_ * NTOT];
__device__ int   g_tidx[B_ * KSEL];
__device__ float g_rowmain[B_];
__device__ float g_rowextra[B_];

// ---------------- helpers ----------------------------------------------------
__device__ __forceinline__ uint32_t smem_to_u32(const void* p) {
    uint32_t a;
    asm("{ .reg .u64 t; cvta.to.shared.u64 t, %1; cvt.u32.u64 %0, t; }" : "=r"(a) : "l"(p));
    return a;
}

#define LDSM_X4(R, ADDR) \
    asm volatile("ldmatrix.sync.aligned.m8n8.x4.shared.b16 {%0,%1,%2,%3}, [%4];" \
        : "=r"((R)[0]), "=r"((R)[1]), "=r"((R)[2]), "=r"((R)[3]) : "r"(ADDR))

#define MMA_TF32(D, A, B0, B1) \
    asm volatile("mma.sync.aligned.m16n8k8.row.col.f32.tf32.tf32.f32 " \
        "{%0,%1,%2,%3}, {%4,%5,%6,%7}, {%8,%9}, {%0,%1,%2,%3};" \
        : "+f"((D)[0]), "+f"((D)[1]), "+f"((D)[2]), "+f"((D)[3]) \
        : "r"((A)[0]), "r"((A)[1]), "r"((A)[2]), "r"((A)[3]), "r"(B0), "r"(B1))

#define CP_ASYNC16(dst, src) \
    asm volatile("cp.async.cg.shared.global [%0], [%1], 16;" :: "r"(dst), "l"(src))
#define CP_COMMIT() asm volatile("cp.async.commit_group;" ::: "memory")
#define CP_WAIT2()  asm volatile("cp.async.wait_group 2;" ::: "memory")

__device__ __forceinline__ float blockReduceSum(float v) {
    int lane = threadIdx.x & 31, wid = threadIdx.x >> 5;
#pragma unroll
    for (int o = 16; o; o >>= 1) v += __shfl_down_sync(0xffffffffu, v, o);
    __shared__ float sh[32];
    if (lane == 0) sh[wid] = v;
    __syncthreads();
    int nw = (blockDim.x + 31) >> 5;
    v = (threadIdx.x < nw) ? sh[threadIdx.x] : 0.f;
    if (wid == 0) {
#pragma unroll
        for (int o = 16; o; o >>= 1) v += __shfl_down_sync(0xffffffffu, v, o);
    }
    return v;
}

// ---------------- kernel 1: square features + query norms --------------------
__global__ void __launch_bounds__(256) sq_kernel(const float* __restrict__ f_s,
                                                 const float* __restrict__ f_t) {
    int r = blockIdx.x;
    const float4* src;
    float4* dst;
    if (r < B_) { src = (const float4*)(f_s + (size_t)r * D_); dst = (float4*)(g_fsq + (size_t)r * D_); }
    else        { src = (const float4*)(f_t + (size_t)(r - B_) * D_); dst = (float4*)(g_ftq + (size_t)(r - B_) * D_); }
    float p = 0.f;
#pragma unroll
    for (int u = 0; u < 2; u++) {
        int i = threadIdx.x + u * 256;
        float4 v = src[i];
        float4 s = make_float4(v.x * v.x, v.y * v.y, v.z * v.z, v.w * v.w);
        dst[i] = s;
        p += s.x * s.x + s.y * s.y + s.z * s.z + s.w * s.w;
    }
    float tot = blockReduceSum(p);
    if (threadIdx.x == 0) {
        if (r < B_) g_qns[r] = tot; else g_qnt[r - B_] = tot;
    }
}

// ---------------- kernel 2: gallery (+ appended ftq) row norms ---------------
__global__ void __launch_bounds__(256) galnorm_kernel(const float* __restrict__ gallery,
                                                      const float* __restrict__ f_t) {
    int n = blockIdx.x;
    float p = 0.f;
    if (n < N0_) {
        const float4* g = (const float4*)(gallery + (size_t)n * D_);
#pragma unroll
        for (int u = 0; u < 2; u++) {
            float4 v = g[threadIdx.x + u * 256];
            p += v.x * v.x + v.y * v.y + v.z * v.z + v.w * v.w;
        }
    } else {
        const float4* g = (const float4*)(f_t + (size_t)(n - N0_) * D_);
#pragma unroll
        for (int u = 0; u < 2; u++) {
            float4 v = g[threadIdx.x + u * 256];
            float4 s = make_float4(v.x * v.x, v.y * v.y, v.z * v.z, v.w * v.w);
            p += s.x * s.x + s.y * s.y + s.z * s.z + s.w * s.w;
        }
    }
    float tot = blockReduceSum(p);
    if (threadIdx.x == 0) g_gn[n] = tot;
}

// ---------------- kernel 3: TF32 mma.sync GEMM with cp.async pipeline --------
// CTA 128(M) x 128(N), 8 warps 2x4, warp tile 64x32, K-chunk 32, 4-stage.
// smem word(r, k) = r*32 + (((k>>2) ^ (r&7))<<2) + (k&3); raw f32 bits fed as
// tf32 (selection-grade precision only; values recomputed in fp32 later).
#define KC 32
#define NSTAGE 4
#define STAGE_B 32768
#define GEMM_SMEM (NSTAGE * STAGE_B)

__global__ void __launch_bounds__(256) tf32_gemm_kernel(const float* __restrict__ gallery) {
    extern __shared__ float smem[];
    const int tid = threadIdx.x;
    const int ntile = blockIdx.x;    // 0..63
    const int mtile = blockIdx.y;    // 0..1

    // staging mapping: thread -> (row, 16-col half)
    const int r  = tid >> 1;
    const int h  = tid & 1;
    const int rx = r & 7;
    const float* aptr = g_ftq + (size_t)(mtile * 128 + r) * D_ + h * 16;
    const int grow = ntile * 128 + r;
    const float* bptr = ((grow < N0_) ? (gallery + (size_t)grow * D_)
                                      : (g_ftq + (size_t)(grow - N0_) * D_)) + h * 16;

    const uint32_t smem_u32 = smem_to_u32(smem);
    const uint32_t st_row = (uint32_t)r * 128u;  // bytes within stage
    uint32_t dsw[4];
#pragma unroll
    for (int u = 0; u < 4; u++) dsw[u] = (uint32_t)(((h * 4 + u) ^ rx) << 4);

    // fragment mapping
    const int lane = tid & 31, wid = tid >> 5;
    const int wm = wid >> 2, wn = wid & 3;
    const int r_in   = lane & 7;
    const int a_moff = ((lane >> 3) & 1) << 3;
    const int a_koff = (lane >> 4) & 1;
    const int b_noff = ((lane >> 4) & 1) << 3;
    const int b_koff = (lane >> 3) & 1;
    const uint32_t arow = (uint32_t)(wm * 64 + r_in + a_moff) * 128u;
    const uint32_t brow = (uint32_t)(wn * 32 + r_in + b_noff) * 128u + 16384u;

    float d[4][4][4];
#pragma unroll
    for (int i = 0; i < 4; i++)
#pragma unroll
        for (int j = 0; j < 4; j++)
#pragma unroll
            for (int q = 0; q < 4; q++) d[i][j][q] = 0.f;

    const int NCH = D_ / KC;  // 64

    // prologue: issue chunks 0..NSTAGE-2
#pragma unroll
    for (int s = 0; s < NSTAGE - 1; s++) {
        const uint32_t ab = smem_u32 + (uint32_t)s * STAGE_B + st_row;
        const float* ap = aptr + s * KC;
        const float* bp = bptr + s * KC;
#pragma unroll
        for (int u = 0; u < 4; u++) CP_ASYNC16(ab + dsw[u], ap + u * 4);
#pragma unroll
        for (int u = 0; u < 4; u++) CP_ASYNC16(ab + 16384u + dsw[u], bp + u * 4);
        CP_COMMIT();
    }

    for (int c = 0; c < NCH; ++c) {
        CP_WAIT2();
        __syncthreads();

        const uint32_t st = (uint32_t)(c & (NSTAGE - 1)) * STAGE_B;
        const uint32_t abase = smem_u32 + st + arow;
        const uint32_t bbase = smem_u32 + st + brow;
#pragma unroll
        for (int s = 0; s < 4; ++s) {
            const uint32_t ka = (uint32_t)(((2 * s + a_koff) ^ r_in) << 4);
            const uint32_t kb = (uint32_t)(((2 * s + b_koff) ^ r_in) << 4);
            uint32_t a[4][4], bb[2][4];
#pragma unroll
            for (int mi = 0; mi < 4; mi++) LDSM_X4(a[mi], abase + mi * 2048 + ka);
#pragma unroll
            for (int np = 0; np < 2; np++) LDSM_X4(bb[np], bbase + np * 2048 + kb);
#pragma unroll
            for (int mi = 0; mi < 4; mi++) {
                MMA_TF32(d[mi][0], a[mi], bb[0][0], bb[0][1]);
                MMA_TF32(d[mi][1], a[mi], bb[0][2], bb[0][3]);
                MMA_TF32(d[mi][2], a[mi], bb[1][0], bb[1][1]);
                MMA_TF32(d[mi][3], a[mi], bb[1][2], bb[1][3]);
            }
        }

        const int nc = c + NSTAGE - 1;
        if (nc < NCH) {
            const uint32_t ab = smem_u32 + (uint32_t)(nc & (NSTAGE - 1)) * STAGE_B + st_row;
            const float* ap = aptr + nc * KC;
            const float* bp = bptr + nc * KC;
#pragma unroll
            for (int u = 0; u < 4; u++) CP_ASYNC16(ab + dsw[u], ap + u * 4);
#pragma unroll
            for (int u = 0; u < 4; u++) CP_ASYNC16(ab + 16384u + dsw[u], bp + u * 4);
        }
        CP_COMMIT();  // unconditional: keeps wait_group bookkeeping exact in the tail
    }

    // epilogue: d2 = |q|^2 + |g|^2 - 2*dot
    const int g = lane >> 2, t = lane & 3;
#pragma unroll
    for (int mi = 0; mi < 4; mi++) {
        const int r0 = mtile * 128 + wm * 64 + mi * 16 + g;
        const int r1 = r0 + 8;
        const float qn0 = g_qnt[r0], qn1 = g_qnt[r1];
        float* o0 = g_d2t + (size_t)r0 * NTOT;
        float* o1 = g_d2t + (size_t)r1 * NTOT;
#pragma unroll
        for (int ni = 0; ni < 4; ni++) {
            const int c0 = ntile * 128 + wn * 32 + ni * 8 + 2 * t;
            const float gn0 = g_gn[c0], gn1 = g_gn[c0 + 1];
            float2 v0, v1;
            v0.x = qn0 + gn0 - 2.f * d[mi][ni][0];
            v0.y = qn0 + gn1 - 2.f * d[mi][ni][1];
            v1.x = qn1 + gn0 - 2.f * d[mi][ni][2];
            v1.y = qn1 + gn1 - 2.f * d[mi][ni][3];
            *(float2*)(o0 + c0) = v0;
            *(float2*)(o1 + c0) = v1;
        }
    }
}

// ---------------- kernel 4: top-K index selection (2-level radix + bitonic) --
template <int NB>
__device__ void find_bin(unsigned* hist, unsigned T, int* s_bin, unsigned* s_pre) {
    constexpr int CH = NB / 256;
    const int tid = threadIdx.x;
    unsigned cnts[CH];
    unsigned local = 0;
#pragma unroll
    for (int c = 0; c < CH; c++) { cnts[c] = hist[tid * CH + c]; local += cnts[c]; }
    unsigned inc = local;
    const int lane = tid & 31, wid = tid >> 5;
#pragma unroll
    for (int off = 1; off < 32; off <<= 1) {
        unsigned n = __shfl_up_sync(0xffffffffu, inc, off);
        if (lane >= off) inc += n;
    }
    __shared__ unsigned wsum[8];
    if (lane == 31) wsum[wid] = inc;
    __syncthreads();
    if (tid == 0) {
        unsigned run = 0;
        for (int w = 0; w < 8; w++) { unsigned t = wsum[w]; wsum[w] = run; run += t; }
    }
    __syncthreads();
    unsigned excl = inc - local + wsum[wid];
    if (excl < T && T <= excl + local) {
        unsigned run = excl;
        for (int c = 0; c < CH; c++) {
            if (run + cnts[c] >= T) { *s_bin = tid * CH + c; *s_pre = run; break; }
            run += cnts[c];
        }
    }
    __syncthreads();
}

__global__ void __launch_bounds__(256) topk_kernel() {
    const int b = blockIdx.x;
    const int tid = threadIdx.x;
    __shared__ unsigned hist[4096];
    __shared__ unsigned long long cand[1024];
    __shared__ int s_bin1, s_bin2;
    __shared__ unsigned s_pre1, s_pre2;
    __shared__ unsigned candCnt;

    const float* row = g_d2t + (size_t)b * NTOT;

    for (int i = tid; i < 2048; i += 256) hist[i] = 0;
    if (tid == 0) candCnt = 0;
    __syncthreads();
    for (int i = tid; i < NTOT; i += 256) {
        unsigned key = __float_as_uint(fmaxf(row[i], EPS_F));
        atomicAdd(&hist[key >> 20], 1u);
    }
    __syncthreads();
    find_bin<2048>(hist, KSEL, &s_bin1, &s_pre1);

    for (int i = tid; i < 4096; i += 256) hist[i] = 0;
    __syncthreads();
    const unsigned bin1 = (unsigned)s_bin1;
    for (int i = tid; i < NTOT; i += 256) {
        unsigned key = __float_as_uint(fmaxf(row[i], EPS_F));
        if ((key >> 20) == bin1) atomicAdd(&hist[(key >> 8) & 0xFFFu], 1u);
    }
    __syncthreads();
    find_bin<4096>(hist, KSEL - s_pre1, &s_bin2, &s_pre2);

    const unsigned bin2 = (unsigned)s_bin2;
    for (int i = tid; i < NTOT; i += 256) {
        unsigned key = __float_as_uint(fmaxf(row[i], EPS_F));
        unsigned hi = key >> 20;
        bool take = (hi < bin1) || (hi == bin1 && ((key >> 8) & 0xFFFu) <= bin2);
        if (take) {
            unsigned pos = atomicAdd(&candCnt, 1u);
            if (pos < 1024) cand[pos] = ((unsigned long long)key << 32) | (unsigned)i;
        }
    }
    __syncthreads();

    int M = (int)candCnt;
    if (M > 1024) M = 1024;
    int S = 256;
    while (S < M) S <<= 1;
    for (int i = tid; i < S; i += 256)
        if (i >= M) cand[i] = 0xFFFFFFFFFFFFFFFFULL;
    __syncthreads();
    for (int ksz = 2; ksz <= S; ksz <<= 1) {
        for (int j = ksz >> 1; j > 0; j >>= 1) {
            for (int i = tid; i < S; i += 256) {
                int ixj = i ^ j;
                if (ixj > i) {
                    unsigned long long a = cand[i], cc = cand[ixj];
                    bool up = ((i & ksz) == 0);
                    if ((a > cc) == up) { cand[i] = cc; cand[ixj] = a; }
                }
            }
            __syncthreads();
        }
    }

    if (tid < KSEL)
        g_tidx[b * KSEL + tid] = (int)(unsigned)(cand[tid] & 0xFFFFFFFFu);
}

// ---------------- kernel 5: fp32 recompute + sort + rank loss (fused) --------
// One block per query row b. Recomputes teacher & student d2 in fp32 for the
// 128 selected indices (single gallery pass), sorts by (fp32 t-key, slot),
// then computes main + smooth-rank losses.
__global__ void __launch_bounds__(256) stfuse_kernel(const float* __restrict__ gallery) {
    const int b = blockIdx.x;
    const int tid = threadIdx.x;
    const int lane = tid & 31, wid = tid >> 5;

    __shared__ float qs[D_], qt[D_];
    __shared__ int   s_idx[KSEL];
    __shared__ float s_sd2[KSEL];
    __shared__ unsigned long long s_key[KSEL];
    __shared__ float tv[KSEL], sv[KSEL];

    // load query rows + indices
    {
        const float4* ps = (const float4*)(g_fsq + (size_t)b * D_);
        const float4* pt = (const float4*)(g_ftq + (size_t)b * D_);
#pragma unroll
        for (int u = 0; u < 2; u++) {
            ((float4*)qs)[tid + u * 256] = ps[tid + u * 256];
            ((float4*)qt)[tid + u * 256] = pt[tid + u * 256];
        }
        if (tid < KSEL) s_idx[tid] = g_tidx[b * KSEL + tid];
    }
    __syncthreads();

    const float qns = g_qns[b], qnt = g_qnt[b];

    // 8 warps x 16 indices: both dots in one gallery pass
    for (int kk = wid; kk < KSEL; kk += 8) {
        const int id = s_idx[kk];
        const float* g = (id < N0_) ? (gallery + (size_t)id * D_)
                                    : (g_ftq + (size_t)(id - N0_) * D_);
        const float4* g4 = (const float4*)g;
        float ds = 0.f, dt = 0.f;
#pragma unroll 4
        for (int i = lane; i < D_ / 4; i += 32) {
            float4 gv = g4[i];
            float4 a = ((const float4*)qs)[i];
            float4 t = ((const float4*)qt)[i];
            ds += a.x * gv.x + a.y * gv.y + a.z * gv.z + a.w * gv.w;
            dt += t.x * gv.x + t.y * gv.y + t.z * gv.z + t.w * gv.w;
        }
#pragma unroll
        for (int o = 16; o; o >>= 1) {
            ds += __shfl_down_sync(0xffffffffu, ds, o);
            dt += __shfl_down_sync(0xffffffffu, dt, o);
        }
        if (lane == 0) {
            const float gn = g_gn[id];
            s_sd2[kk] = fmaxf(qns + gn - 2.f * ds, EPS_F);
            float td2 = fmaxf(qnt + gn - 2.f * dt, EPS_F);
            s_key[kk] = ((unsigned long long)__float_as_uint(td2) << 32) | (unsigned)kk;
        }
    }
    __syncthreads();

    // bitonic sort of 128 (t-key, slot) pairs, ascending
    for (int ksz = 2; ksz <= KSEL; ksz <<= 1) {
        for (int j = ksz >> 1; j > 0; j >>= 1) {
            if (tid < KSEL) {
                int ixj = tid ^ j;
                if (ixj > tid) {
                    unsigned long long a = s_key[tid], c = s_key[ixj];
                    bool up = ((tid & ksz) == 0);
                    if ((a > c) == up) { s_key[tid] = c; s_key[ixj] = a; }
                }
            }
            __syncthreads();
        }
    }

    // unpack: sorted t values; student values permuted to sorted-t order
    if (tid < KSEL) {
        unsigned long long e = s_key[tid];
        tv[tid] = sqrtf(__uint_as_float((unsigned)(e >> 32)));
        sv[tid] = sqrtf(s_sd2[(unsigned)(e & 0xFFFFFFFFu)]);
    }
    __syncthreads();

    // smooth-rank L2 over entries 1..127
    float p = 0.f;
    if (tid >= 1 && tid < KSEL) {
        const float ti = tv[tid], si = sv[tid];
        float tr = 0.f, sr = 0.f;
#pragma unroll 4
        for (int j = 1; j < KSEL; j++) {
            tr += fmaxf(ti - tv[j], 0.f);
            sr += fmaxf(si - sv[j], 0.f);
        }
        const float dd = tr - sr;
        p = dd * dd;
    }
    const float s = blockReduceSum(p);
    if (tid == 0) {
        g_rowextra[b] = sqrtf(s);
        g_rowmain[b]  = fabsf(sv[0] - tv[0]);
    }
}

// ---------------- kernel 6: deterministic final reduction ---------------------
__global__ void __launch_bounds__(256) final_kernel(float* __restrict__ out) {
    __shared__ float sm[256], se[256];
    const int t = threadIdx.x;
    sm[t] = g_rowmain[t];
    se[t] = g_rowextra[t];
    __syncthreads();
    for (int s = 128; s > 0; s >>= 1) {
        if (t < s) { sm[t] += sm[t + s]; se[t] += se[t + s]; }
        __syncthreads();
    }
    if (t == 0) {
        float main_loss  = sm[0] / (float)B_;
        float extra_loss = (se[0] / (float)B_) / (float)(KSEL - 1);
        out[0] = main_loss + extra_loss;
    }
}

// ---------------- launch ------------------------------------------------------
extern "C" void kernel_launch(void* const* d_in, const int* in_sizes, int n_in,
                              void* d_out, int out_size) {
    const float* f_s     = (const float*)d_in[0];
    const float* f_t     = (const float*)d_in[1];
    const float* gallery = (const float*)d_in[2];
    float* out = (float*)d_out;

    cudaFuncSetAttribute(tf32_gemm_kernel, cudaFuncAttributeMaxDynamicSharedMemorySize, GEMM_SMEM);

    sq_kernel<<<512, 256>>>(f_s, f_t);
    galnorm_kernel<<<NTOT, 256>>>(gallery, f_t);
    tf32_gemm_kernel<<<dim3(NTOT / 128, B_ / 128), 256, GEMM_SMEM>>>(gallery);
    topk_kernel<<<B_, 256>>>();
    stfuse_kernel<<<B_, 256>>>(gallery);
    final_kernel<<<1, 256>>>(out);
}

// round 5
// speedup vs baseline: 2.8079x; 1.0965x over previous
#include <cuda_runtime.h>
#include <cuda_bf16.h>
#include <cstdint>

// Problem constants
#define B_    256
#define D_    2048
#define N0_   7936
#define NTOT  8192
#define KSEL  128
#define NSEL  160          // selection margin: collect >= 160 noisy-smallest
#define CAND_MAX 256
#define EPS_F 1e-12f
#define KEY_OFF 0x45800    // (bits of 4096.0f) >> 12

// ---------------- scratch ----------------------------------------------------
__device__ float    g_fsq[B_ * D_];             // f_s^2 (fp32, for student dots)
__device__ float    g_ftq[B_ * D_];             // f_t^2 (fp32, for teacher dots)
__device__ uint16_t g_ftq_bf[B_ * D_];          // f_t^2 bf16 (GEMM A + B tail)
__device__ uint16_t g_gal_bf[(size_t)N0_ * D_]; // gallery bf16 (GEMM B)
__device__ float    g_qns[B_];
__device__ float    g_qnt[B_];
__device__ float    g_gn[NTOT];
__device__ uint16_t g_key[(size_t)B_ * NTOT];   // quantized d2 keys
__device__ int      g_cand[B_ * CAND_MAX];
__device__ int      g_candn[B_];
__device__ float    g_rowmain[B_];
__device__ float    g_rowextra[B_];

// ---------------- PTX helpers -------------------------------------------------
__device__ __forceinline__ uint32_t smem_to_u32(const void* p) {
    uint32_t a;
    asm("{ .reg .u64 t; cvta.to.shared.u64 t, %1; cvt.u32.u64 %0, t; }" : "=r"(a) : "l"(p));
    return a;
}

#define LDSM_X4(R, ADDR) \
    asm volatile("ldmatrix.sync.aligned.m8n8.x4.shared.b16 {%0,%1,%2,%3}, [%4];" \
        : "=r"((R)[0]), "=r"((R)[1]), "=r"((R)[2]), "=r"((R)[3]) : "r"(ADDR))

#define MMA_BF16(D, A, B0, B1) \
    asm volatile("mma.sync.aligned.m16n8k16.row.col.f32.bf16.bf16.f32 " \
        "{%0,%1,%2,%3}, {%4,%5,%6,%7}, {%8,%9}, {%0,%1,%2,%3};" \
        : "+f"((D)[0]), "+f"((D)[1]), "+f"((D)[2]), "+f"((D)[3]) \
        : "r"((A)[0]), "r"((A)[1]), "r"((A)[2]), "r"((A)[3]), "r"(B0), "r"(B1))

#define CP_ASYNC16(dst, src) \
    asm volatile("cp.async.cg.shared.global [%0], [%1], 16;" :: "r"(dst), "l"(src))
#define CP_COMMIT() asm volatile("cp.async.commit_group;" ::: "memory")
#define CP_WAIT2()  asm volatile("cp.async.wait_group 2;" ::: "memory")

__device__ __forceinline__ float blockReduceSum(float v) {
    int lane = threadIdx.x & 31, wid = threadIdx.x >> 5;
#pragma unroll
    for (int o = 16; o; o >>= 1) v += __shfl_down_sync(0xffffffffu, v, o);
    __shared__ float sh[32];
    if (lane == 0) sh[wid] = v;
    __syncthreads();
    int nw = (blockDim.x + 31) >> 5;
    v = (threadIdx.x < nw) ? sh[threadIdx.x] : 0.f;
    if (wid == 0) {
#pragma unroll
        for (int o = 16; o; o >>= 1) v += __shfl_down_sync(0xffffffffu, v, o);
    }
    return v;
}

__device__ __forceinline__ uint32_t pack_bf2(float a, float b) {
    return (uint32_t)__bfloat16_as_ushort(__float2bfloat16(a)) |
           ((uint32_t)__bfloat16_as_ushort(__float2bfloat16(b)) << 16);
}

// ---------------- kernel 1: square features + norms (+ftq bf16) --------------
__global__ void __launch_bounds__(256) sq_kernel(const float* __restrict__ f_s,
                                                 const float* __restrict__ f_t) {
    int r = blockIdx.x;  // 0..511
    float p = 0.f;
    if (r < B_) {
        const float4* src = (const float4*)(f_s + (size_t)r * D_);
        float4* dst = (float4*)(g_fsq + (size_t)r * D_);
#pragma unroll
        for (int u = 0; u < 2; u++) {
            int i = threadIdx.x + u * 256;
            float4 v = src[i];
            float4 s = make_float4(v.x * v.x, v.y * v.y, v.z * v.z, v.w * v.w);
            dst[i] = s;
            p += s.x * s.x + s.y * s.y + s.z * s.z + s.w * s.w;
        }
    } else {
        const int rr = r - B_;
        const float4* src = (const float4*)(f_t + (size_t)rr * D_);
        float4* dst = (float4*)(g_ftq + (size_t)rr * D_);
        uint4* dbf = (uint4*)(g_ftq_bf + (size_t)rr * D_);
#pragma unroll
        for (int u = 0; u < 2; u++) {
            int i = threadIdx.x * 2 + u;   // 8 consecutive floats per thread
            float4 v0 = src[i];
            float4 s0 = make_float4(v0.x * v0.x, v0.y * v0.y, v0.z * v0.z, v0.w * v0.w);
            dst[i] = s0;
            p += s0.x * s0.x + s0.y * s0.y + s0.z * s0.z + s0.w * s0.w;
            if (u == 0) {
                float4 v1 = src[i + 1];
                float4 s1 = make_float4(v1.x * v1.x, v1.y * v1.y, v1.z * v1.z, v1.w * v1.w);
                dst[i + 1] = s1;
                p += s1.x * s1.x + s1.y * s1.y + s1.z * s1.z + s1.w * s1.w;
                uint4 bf;
                bf.x = pack_bf2(s0.x, s0.y); bf.y = pack_bf2(s0.z, s0.w);
                bf.z = pack_bf2(s1.x, s1.y); bf.w = pack_bf2(s1.z, s1.w);
                dbf[threadIdx.x] = bf;
                u = 1;  // consumed both halves
            }
        }
    }
    float tot = blockReduceSum(p);
    if (threadIdx.x == 0) {
        if (r < B_) g_qns[r] = tot; else g_qnt[r - B_] = tot;
    }
}

// ---------------- kernel 2: gallery norms + bf16 copy -------------------------
__global__ void __launch_bounds__(256) galnorm_kernel(const float* __restrict__ gallery,
                                                      const float* __restrict__ f_t) {
    int n = blockIdx.x;
    float p = 0.f;
    if (n < N0_) {
        const float4* g = (const float4*)(gallery + (size_t)n * D_);
        uint4* dbf = (uint4*)(g_gal_bf + (size_t)n * D_);
        float4 v0 = g[threadIdx.x * 2], v1 = g[threadIdx.x * 2 + 1];
        p += v0.x * v0.x + v0.y * v0.y + v0.z * v0.z + v0.w * v0.w;
        p += v1.x * v1.x + v1.y * v1.y + v1.z * v1.z + v1.w * v1.w;
        uint4 bf;
        bf.x = pack_bf2(v0.x, v0.y); bf.y = pack_bf2(v0.z, v0.w);
        bf.z = pack_bf2(v1.x, v1.y); bf.w = pack_bf2(v1.z, v1.w);
        dbf[threadIdx.x] = bf;
    } else {
        const float4* g = (const float4*)(f_t + (size_t)(n - N0_) * D_);
#pragma unroll
        for (int u = 0; u < 2; u++) {
            float4 v = g[threadIdx.x + u * 256];
            float4 s = make_float4(v.x * v.x, v.y * v.y, v.z * v.z, v.w * v.w);
            p += s.x * s.x + s.y * s.y + s.z * s.z + s.w * s.w;
        }
    }
    float tot = blockReduceSum(p);
    if (threadIdx.x == 0) g_gn[n] = tot;
}

// ---------------- kernel 3: bf16 mma.sync GEMM -> quantized keys --------------
// CTA 128(M) x 128(N), 8 warps 2x4, warp tile 64x32, K-chunk 64, 4-stage cp.async.
// smem row = 128 bytes (64 bf16), 8 groups of 16B, group swizzle g ^ (row&7).
#define KC 64
#define NSTAGE 4
#define STAGE_B 32768
#define GEMM_SMEM (NSTAGE * STAGE_B)

__global__ void __launch_bounds__(256) bf16_gemm_kernel() {
    extern __shared__ char smem[];
    const int tid = threadIdx.x;
    const int ntile = blockIdx.x;    // 0..63
    const int mtile = blockIdx.y;    // 0..1

    // staging: thread -> (row r, half h). 8 x cp.async(16B) per stage.
    const int r  = tid >> 1;
    const int h  = tid & 1;
    const uint16_t* aptr = g_ftq_bf + (size_t)(mtile * 128 + r) * D_ + h * 32;
    const int grow = ntile * 128 + r;
    const uint16_t* bptr = ((grow < N0_) ? (g_gal_bf + (size_t)grow * D_)
                                         : (g_ftq_bf + (size_t)(grow - N0_) * D_)) + h * 32;
    const uint32_t smem_u32 = smem_to_u32(smem);
    const uint32_t st_row = (uint32_t)r * 128u;
    uint32_t dsw[4];
#pragma unroll
    for (int u = 0; u < 4; u++) dsw[u] = (uint32_t)(((h * 4 + u) ^ (r & 7)) << 4);

    // fragment mapping
    const int lane = tid & 31, wid = tid >> 5;
    const int wm = wid >> 2, wn = wid & 3;
    const int m_in   = lane & 15;                        // A row within frag pair
    const int a_ksel = (lane >> 4) & 1;                  // A k-group select
    const int n_in   = (lane & 7) + ((lane >> 4) & 1) * 8;  // B row
    const int b_ksel = (lane >> 3) & 1;                  // B k-group select
    const uint32_t a_base = (uint32_t)(wm * 64 + m_in) * 128u;
    const uint32_t b_base = 16384u + (uint32_t)(wn * 32 + n_in) * 128u;
    const uint32_t a_sw = (uint32_t)(m_in & 7);
    const uint32_t b_sw = (uint32_t)(n_in & 7);

    float d[4][4][4];
#pragma unroll
    for (int i = 0; i < 4; i++)
#pragma unroll
        for (int j = 0; j < 4; j++)
#pragma unroll
            for (int q = 0; q < 4; q++) d[i][j][q] = 0.f;

    const int NCH = D_ / KC;  // 32

    // prologue: stages 0..2
#pragma unroll
    for (int s = 0; s < NSTAGE - 1; s++) {
        const uint32_t ab = smem_u32 + (uint32_t)s * STAGE_B + st_row;
        const uint16_t* ap = aptr + s * KC;
        const uint16_t* bp = bptr + s * KC;
#pragma unroll
        for (int u = 0; u < 4; u++) CP_ASYNC16(ab + dsw[u], ap + u * 8);
#pragma unroll
        for (int u = 0; u < 4; u++) CP_ASYNC16(ab + 16384u + dsw[u], bp + u * 8);
        CP_COMMIT();
    }

    for (int c = 0; c < NCH; ++c) {
        CP_WAIT2();
        __syncthreads();

        const uint32_t st = smem_u32 + (uint32_t)(c & (NSTAGE - 1)) * STAGE_B;
        const uint32_t abase = st + a_base;
        const uint32_t bbase = st + b_base;
#pragma unroll
        for (int s = 0; s < 4; ++s) {  // 4 k16 steps per K64 chunk
            const uint32_t ka = (uint32_t)(((2 * s + a_ksel) ^ a_sw) << 4);
            const uint32_t kb = (uint32_t)(((2 * s + b_ksel) ^ b_sw) << 4);
            uint32_t a[4][4], bb[2][4];
#pragma unroll
            for (int mi = 0; mi < 4; mi++) LDSM_X4(a[mi], abase + mi * 2048 + ka);
#pragma unroll
            for (int np = 0; np < 2; np++) LDSM_X4(bb[np], bbase + np * 2048 + kb);
#pragma unroll
            for (int mi = 0; mi < 4; mi++) {
                MMA_BF16(d[mi][0], a[mi], bb[0][0], bb[0][1]);
                MMA_BF16(d[mi][1], a[mi], bb[0][2], bb[0][3]);
                MMA_BF16(d[mi][2], a[mi], bb[1][0], bb[1][1]);
                MMA_BF16(d[mi][3], a[mi], bb[1][2], bb[1][3]);
            }
        }

        const int nc = c + NSTAGE - 1;
        if (nc < NCH) {
            const uint32_t ab = smem_u32 + (uint32_t)(nc & (NSTAGE - 1)) * STAGE_B + st_row;
            const uint16_t* ap = aptr + nc * KC;
            const uint16_t* bp = bptr + nc * KC;
#pragma unroll
            for (int u = 0; u < 4; u++) CP_ASYNC16(ab + dsw[u], ap + u * 8);
#pragma unroll
            for (int u = 0; u < 4; u++) CP_ASYNC16(ab + 16384u + dsw[u], bp + u * 8);
        }
        CP_COMMIT();
    }

    // epilogue: d2 -> quantized u16 key
    const int g = lane >> 2, t = lane & 3;
#pragma unroll
    for (int mi = 0; mi < 4; mi++) {
        const int r0 = mtile * 128 + wm * 64 + mi * 16 + g;
        const int r1 = r0 + 8;
        const float qn0 = g_qnt[r0], qn1 = g_qnt[r1];
        uint16_t* o0 = g_key + (size_t)r0 * NTOT;
        uint16_t* o1 = g_key + (size_t)r1 * NTOT;
#pragma unroll
        for (int ni = 0; ni < 4; ni++) {
            const int c0 = ntile * 128 + wn * 32 + ni * 8 + 2 * t;
            const float gn0 = g_gn[c0], gn1 = g_gn[c0 + 1];
            float v00 = qn0 + gn0 - 2.f * d[mi][ni][0];
            float v01 = qn0 + gn1 - 2.f * d[mi][ni][1];
            float v10 = qn1 + gn0 - 2.f * d[mi][ni][2];
            float v11 = qn1 + gn1 - 2.f * d[mi][ni][3];
            int k00 = (int)(__float_as_uint(fmaxf(v00, EPS_F)) >> 12) - KEY_OFF;
            int k01 = (int)(__float_as_uint(fmaxf(v01, EPS_F)) >> 12) - KEY_OFF;
            int k10 = (int)(__float_as_uint(fmaxf(v10, EPS_F)) >> 12) - KEY_OFF;
            int k11 = (int)(__float_as_uint(fmaxf(v11, EPS_F)) >> 12) - KEY_OFF;
            k00 = min(max(k00, 0), 65535); k01 = min(max(k01, 0), 65535);
            k10 = min(max(k10, 0), 65535); k11 = min(max(k11, 0), 65535);
            *(uint32_t*)(o0 + c0) = (uint32_t)k00 | ((uint32_t)k01 << 16);
            *(uint32_t*)(o1 + c0) = (uint32_t)k10 | ((uint32_t)k11 << 16);
        }
    }
}

// ---------------- kernel 4: candidate selection (1 histogram + collect) ------
__global__ void __launch_bounds__(256) select_kernel() {
    const int b = blockIdx.x;
    const int tid = threadIdx.x;
    __shared__ unsigned hist[4096];
    __shared__ int s_bin;
    __shared__ unsigned candCnt;

    const uint16_t* row = g_key + (size_t)b * NTOT;
    for (int i = tid; i < 4096; i += 256) hist[i] = 0;
    if (tid == 0) candCnt = 0;
    __syncthreads();

    // histogram (8 keys per uint4 load, 4 loads per thread)
    const uint4* row4 = (const uint4*)row;
#pragma unroll
    for (int u = 0; u < 4; u++) {
        uint4 v = row4[tid + u * 256];
        const uint32_t w[4] = {v.x, v.y, v.z, v.w};
#pragma unroll
        for (int j = 0; j < 4; j++) {
            atomicAdd(&hist[min(w[j] & 0xFFFFu, 4095u)], 1u);
            atomicAdd(&hist[min(w[j] >> 16, 4095u)], 1u);
        }
    }
    __syncthreads();

    // scan for first bin with cumulative >= NSEL
    {
        unsigned cnts[16], local = 0;
#pragma unroll
        for (int c = 0; c < 16; c++) { cnts[c] = hist[tid * 16 + c]; local += cnts[c]; }
        unsigned inc = local;
        const int lane = tid & 31, wid = tid >> 5;
#pragma unroll
        for (int off = 1; off < 32; off <<= 1) {
            unsigned n = __shfl_up_sync(0xffffffffu, inc, off);
            if (lane >= off) inc += n;
        }
        __shared__ unsigned wsum[8];
        if (lane == 31) wsum[wid] = inc;
        __syncthreads();
        if (tid == 0) {
            unsigned run = 0;
            for (int w = 0; w < 8; w++) { unsigned t = wsum[w]; wsum[w] = run; run += t; }
        }
        __syncthreads();
        unsigned excl = inc - local + wsum[wid];
        if (excl < NSEL && NSEL <= excl + local) {
            unsigned run = excl;
            for (int c = 0; c < 16; c++) {
                run += cnts[c];
                if (run >= NSEL) { s_bin = tid * 16 + c; break; }
            }
        }
        __syncthreads();
    }

    // collect all indices with key <= s_bin
    const unsigned thr = (unsigned)s_bin;
#pragma unroll
    for (int u = 0; u < 4; u++) {
        uint4 v = row4[tid + u * 256];
        const uint32_t w[4] = {v.x, v.y, v.z, v.w};
        const int base = (tid + u * 256) * 8;
#pragma unroll
        for (int j = 0; j < 4; j++) {
            if ((w[j] & 0xFFFFu) <= thr) {
                unsigned pos = atomicAdd(&candCnt, 1u);
                if (pos < CAND_MAX) g_cand[b * CAND_MAX + pos] = base + j * 2;
            }
            if ((w[j] >> 16) <= thr) {
                unsigned pos = atomicAdd(&candCnt, 1u);
                if (pos < CAND_MAX) g_cand[b * CAND_MAX + pos] = base + j * 2 + 1;
            }
        }
    }
    __syncthreads();
    if (tid == 0) g_candn[b] = (int)min(candCnt, (unsigned)CAND_MAX);
}

// ---------------- kernel 5: fp32 recompute + exact top-K + rank loss ----------
__global__ void __launch_bounds__(256) stfuse_kernel(const float* __restrict__ gallery) {
    const int b = blockIdx.x;
    const int tid = threadIdx.x;
    const int lane = tid & 31, wid = tid >> 5;

    __shared__ float qs[D_], qt[D_];
    __shared__ int   s_idx[CAND_MAX];
    __shared__ float s_sd2[CAND_MAX];
    __shared__ unsigned long long s_key[CAND_MAX];
    __shared__ float tv[KSEL], sv[KSEL];

    const int C = g_candn[b];
    {
        const float4* ps = (const float4*)(g_fsq + (size_t)b * D_);
        const float4* pt = (const float4*)(g_ftq + (size_t)b * D_);
#pragma unroll
        for (int u = 0; u < 2; u++) {
            ((float4*)qs)[tid + u * 256] = ps[tid + u * 256];
            ((float4*)qt)[tid + u * 256] = pt[tid + u * 256];
        }
        if (tid < CAND_MAX) {
            s_idx[tid] = (tid < C) ? g_cand[b * CAND_MAX + tid] : 0;
            s_key[tid] = 0xFFFFFFFFFFFFFFFFULL;
        }
    }
    __syncthreads();

    const float qns = g_qns[b], qnt = g_qnt[b];

    // 8 warps, both dots per candidate in one gallery pass
    for (int kk = wid; kk < C; kk += 8) {
        const int id = s_idx[kk];
        const float* g = (id < N0_) ? (gallery + (size_t)id * D_)
                                    : (g_ftq + (size_t)(id - N0_) * D_);
        const float4* g4 = (const float4*)g;
        float ds = 0.f, dt = 0.f;
#pragma unroll 4
        for (int i = lane; i < D_ / 4; i += 32) {
            float4 gv = g4[i];
            float4 a = ((const float4*)qs)[i];
            float4 t = ((const float4*)qt)[i];
            ds += a.x * gv.x + a.y * gv.y + a.z * gv.z + a.w * gv.w;
            dt += t.x * gv.x + t.y * gv.y + t.z * gv.z + t.w * gv.w;
        }
#pragma unroll
        for (int o = 16; o; o >>= 1) {
            ds += __shfl_down_sync(0xffffffffu, ds, o);
            dt += __shfl_down_sync(0xffffffffu, dt, o);
        }
        if (lane == 0) {
            const float gn = g_gn[id];
            s_sd2[kk] = fmaxf(qns + gn - 2.f * ds, EPS_F);
            float td2 = fmaxf(qnt + gn - 2.f * dt, EPS_F);
            // key: (fp32 d2 bits, gallery idx, slot) -> jax tie-break by index
            s_key[kk] = ((unsigned long long)__float_as_uint(td2) << 32)
                        | ((unsigned)id << 8) | (unsigned)kk;
        }
    }
    __syncthreads();

    // bitonic sort 256 entries ascending (exact fp32 ordering)
    for (int ksz = 2; ksz <= CAND_MAX; ksz <<= 1) {
        for (int j = ksz >> 1; j > 0; j >>= 1) {
            int ixj = tid ^ j;
            if (ixj > tid) {
                unsigned long long a = s_key[tid], c = s_key[ixj];
                bool up = ((tid & ksz) == 0);
                if ((a > c) == up) { s_key[tid] = c; s_key[ixj] = a; }
            }
            __syncthreads();
        }
    }

    // take exact top-128 by fp32 teacher key
    if (tid < KSEL) {
        unsigned long long e = s_key[tid];
        tv[tid] = sqrtf(__uint_as_float((unsigned)(e >> 32)));
        sv[tid] = sqrtf(s_sd2[(unsigned)(e & 0xFFu)]);
    }
    __syncthreads();

    // smooth-rank L2 over entries 1..127
    float p = 0.f;
    if (tid >= 1 && tid < KSEL) {
        const float ti = tv[tid], si = sv[tid];
        float tr = 0.f, sr = 0.f;
#pragma unroll 4
        for (int j = 1; j < KSEL; j++) {
            tr += fmaxf(ti - tv[j], 0.f);
            sr += fmaxf(si - sv[j], 0.f);
        }
        const float dd = tr - sr;
        p = dd * dd;
    }
    const float s = blockReduceSum(p);
    if (tid == 0) {
        g_rowextra[b] = sqrtf(s);
        g_rowmain[b]  = fabsf(sv[0] - tv[0]);
    }
}

// ---------------- kernel 6: deterministic final reduction ---------------------
__global__ void __launch_bounds__(256) final_kernel(float* __restrict__ out) {
    __shared__ float sm[256], se[256];
    const int t = threadIdx.x;
    sm[t] = g_rowmain[t];
    se[t] = g_rowextra[t];
    __syncthreads();
    for (int s = 128; s > 0; s >>= 1) {
        if (t < s) { sm[t] += sm[t + s]; se[t] += se[t + s]; }
        __syncthreads();
    }
    if (t == 0) {
        float main_loss  = sm[0] / (float)B_;
        float extra_loss = (se[0] / (float)B_) / (float)(KSEL - 1);
        out[0] = main_loss + extra_loss;
    }
}

// ---------------- launch ------------------------------------------------------
extern "C" void kernel_launch(void* const* d_in, const int* in_sizes, int n_in,
                              void* d_out, int out_size) {
    const float* f_s     = (const float*)d_in[0];
    const float* f_t     = (const float*)d_in[1];
    const float* gallery = (const float*)d_in[2];
    float* out = (float*)d_out;

    cudaFuncSetAttribute(bf16_gemm_kernel, cudaFuncAttributeMaxDynamicSharedMemorySize, GEMM_SMEM);

    sq_kernel<<<512, 256>>>(f_s, f_t);
    galnorm_kernel<<<NTOT, 256>>>(gallery, f_t);
    bf16_gemm_kernel<<<dim3(NTOT / 128, B_ / 128), 256, GEMM_SMEM>>>();
    select_kernel<<<B_, 256>>>();
    stfuse_kernel<<<B_, 256>>>(gallery);
    final_kernel<<<1, 256>>>(out);
}